// round 15
// baseline (speedup 1.0000x reference)
#include <cuda_runtime.h>
#include <cuda_bf16.h>

// Blur = UpFirDn2D(up=2, dn=2, k=4x4) collapses to a 2x2 stencil:
//   out[y][x] = f11*in[y][x] + f13*in[y][x+1] + f31*in[y+1][x] + f33*in[y+1][x+1]
// (zeros past the right/bottom edge).
//
// R13: 256-bit load experiment. 16-lane segment = one image row (16 lanes x
// 8 floats = 128 = W). Each thread loads an 8-float strip of 5 consecutive
// rows via ld.global.nc.v8.b32 (LDG.256, sm_100+), computes 4 output rows,
// stores 2xSTG.128 per row. +8-column neighbor via shfl width=16 (lane 15 of
// each segment = image right edge). Fewer, wider read requests -> probes
// whether the 76% DRAM-busy plateau is request-concurrency-limited.

#define BB 8
#define CC 256
#define HH 128
#define WW 128
#define RR 4   // output rows per task

typedef unsigned int u32;

__device__ __forceinline__ void ldg256(const float* p, float* v) {
    u32 a, b, c, d, e, f, g, h;
    asm volatile("ld.global.nc.v8.b32 {%0,%1,%2,%3,%4,%5,%6,%7}, [%8];"
                 : "=r"(a), "=r"(b), "=r"(c), "=r"(d),
                   "=r"(e), "=r"(f), "=r"(g), "=r"(h)
                 : "l"(p));
    v[0] = __uint_as_float(a); v[1] = __uint_as_float(b);
    v[2] = __uint_as_float(c); v[3] = __uint_as_float(d);
    v[4] = __uint_as_float(e); v[5] = __uint_as_float(f);
    v[6] = __uint_as_float(g); v[7] = __uint_as_float(h);
}

__global__ __launch_bounds__(256, 4) void blur_kernel(
    const float* __restrict__ x,
    const float* __restrict__ filt,
    float* __restrict__ out)
{
    const int sub  = threadIdx.x & 15;          // x-chunk within row: 8 floats
    const int seg  = (blockIdx.x * blockDim.x + threadIdx.x) >> 4;  // 16-lane task id
    // task -> (bc, row-group). Row groups per channel image: H/R = 32.
    const int rg = seg & 31;
    const int bc = seg >> 5;                    // b*C + c
    const int c  = bc & (CC - 1);
    const int y0 = rg << 2;                     // first output row of this group

    // Per-channel taps: uniform across the segment -> broadcast loads.
    const float* fp = filt + c * 16;
    const float w11 = __ldg(fp + 5);
    const float w13 = __ldg(fp + 7);
    const float w31 = __ldg(fp + 13);
    const float w33 = __ldg(fp + 15);

    const size_t base = ((size_t)bc << 14) + ((size_t)y0 << 7) + ((size_t)sub << 3);
    const float* p = x + base;

    // 5 front-batched LDG.256 (32B each, 32B-aligned). Halo row clamped for
    // the last group and zeroed after.
    const bool last = (rg == 31);
    const int off4 = last ? (3 * WW) : (4 * WW);
    float r0[8], r1[8], r2[8], r3[8], r4[8];
    ldg256(p,          r0);
    ldg256(p + WW,     r1);
    ldg256(p + 2 * WW, r2);
    ldg256(p + 3 * WW, r3);
    ldg256(p + off4,   r4);
    if (last) {
#pragma unroll
        for (int j = 0; j < 8; j++) r4[j] = 0.0f;
    }

    // Neighbor x+8 element = next lane's [0], within the 16-lane segment.
    // Lane 15 of the segment is the image right edge -> zero.
    const bool edge = (sub == 15);
    float n0 = __shfl_down_sync(0xffffffffu, r0[0], 1, 16);
    float n1 = __shfl_down_sync(0xffffffffu, r1[0], 1, 16);
    float n2 = __shfl_down_sync(0xffffffffu, r2[0], 1, 16);
    float n3 = __shfl_down_sync(0xffffffffu, r3[0], 1, 16);
    float n4 = __shfl_down_sync(0xffffffffu, r4[0], 1, 16);
    if (edge) { n0 = n1 = n2 = n3 = n4 = 0.0f; }

    float* q = out + base;

#define ROW(I, A, B, NA, NB)                                                \
    {                                                                       \
        float4 lo, hi;                                                      \
        lo.x = w11 * A[0] + w13 * A[1] + w31 * B[0] + w33 * B[1];           \
        lo.y = w11 * A[1] + w13 * A[2] + w31 * B[1] + w33 * B[2];           \
        lo.z = w11 * A[2] + w13 * A[3] + w31 * B[2] + w33 * B[3];           \
        lo.w = w11 * A[3] + w13 * A[4] + w31 * B[3] + w33 * B[4];           \
        hi.x = w11 * A[4] + w13 * A[5] + w31 * B[4] + w33 * B[5];           \
        hi.y = w11 * A[5] + w13 * A[6] + w31 * B[5] + w33 * B[6];           \
        hi.z = w11 * A[6] + w13 * A[7] + w31 * B[6] + w33 * B[7];           \
        hi.w = w11 * A[7] + w13 * NA   + w31 * B[7] + w33 * NB;             \
        *(float4*)(q + (I) * WW)     = lo;                                  \
        *(float4*)(q + (I) * WW + 4) = hi;                                  \
    }

    ROW(0, r0, r1, n0, n1)
    ROW(1, r1, r2, n1, n2)
    ROW(2, r2, r3, n2, n3)
    ROW(3, r3, r4, n3, n4)
#undef ROW
}

extern "C" void kernel_launch(void* const* d_in, const int* in_sizes, int n_in,
                              void* d_out, int out_size)
{
    const float* x    = (const float*)d_in[0];
    const float* filt = (const float*)d_in[1];
    float* out        = (float*)d_out;

    // tasks = B*C*(H/R) = 65536 sixteen-lane segments; 16 per 256-thr block
    const int block = 256;
    const int grid  = (BB * CC * (HH / RR)) / 16;   // 4096
    blur_kernel<<<grid, block>>>(x, filt, out);
}

// round 16
// speedup vs baseline: 1.0478x; 1.0478x over previous
#include <cuda_runtime.h>
#include <cuda_bf16.h>

// Blur = UpFirDn2D(up=2, dn=2, k=4x4) collapses to a 2x2 stencil:
//   out[y][x] = f11*in[y][x] + f13*in[y][x+1] + f31*in[y+1][x] + f33*in[y+1][x+1]
// (zeros past the right/bottom edge). 16x less math than the literal conv;
// the op is pure memory: 134MB read + 134MB write per call.
//
// FINAL: the converged optimum (43.49us bench / 34.8us ncu, best of 9
// measured variants). Warp = one full image row (32 lanes x float4 = 128 =
// W); R=4 output rows per thread from 5 loaded rows; +1-column neighbor via
// __shfl_down (lane 31 = image edge); conditional halo-row load; default
// cache policies; grid 8192 x 256, regs 32, occ ~74%.
//
// Why this is the wall — full evidence matrix, every axis regressed or tied:
//   load width 256b (LDG.256):   70.5% DRAM, MORE L1 wavefronts   (-2.8us)
//   rows/thread 8 @ 32 regs:     loads serialized by ptxas        (-1.4us)
//   rows/thread 8 @ 54 regs:     deep MLP, DRAM% unchanged        (-0.5us)
//   persistent 1-wave grid:      regs 40, occ 60%                 (-2.4us)
//   __stcs streaming stores:     neutral-minus                    (-0.6us)
//   L2 evict_last input loads:   exactly neutral                  ( 0.0us)
// DRAM pinned at 5.9-6.04 TB/s (72-76% busy) across all of them: that is the
// achieved HBM ceiling for this interleaved read/write stream on sm_103a.
// Traffic (~212MB/replay) is at the L2-assisted compulsory floor (cross-
// replay L2 residency serves ~56MB of the input). Bench-vs-ncu delta (~8.6us)
// is fixed harness/graph overhead.

#define BB 8
#define CC 256
#define HH 128
#define WW 128
#define RR 4   // output rows per thread

__global__ __launch_bounds__(256) void blur_kernel(
    const float* __restrict__ x,
    const float* __restrict__ filt,
    float* __restrict__ out)
{
    const int lane    = threadIdx.x & 31;
    const int warp_id = blockIdx.x * (blockDim.x >> 5) + (threadIdx.x >> 5);
    // warp -> (bc, row-group). Row groups per channel image: H/R = 32.
    const int rg = warp_id & 31;
    const int bc = warp_id >> 5;          // b*C + c
    const int c  = bc & (CC - 1);
    const int y0 = rg << 2;               // first output row of this group

    // Per-channel taps: uniform across the warp -> broadcast loads.
    const float* fp = filt + c * 16;
    const float w11 = __ldg(fp + 5);
    const float w13 = __ldg(fp + 7);
    const float w31 = __ldg(fp + 13);
    const float w33 = __ldg(fp + 15);

    const size_t base = ((size_t)bc << 14) + ((size_t)y0 << 7) + ((size_t)lane << 2);
    const float* p = x + base;

    // Load R+1 = 5 input rows (front-batched for MLP).
    float4 r0 = *(const float4*)(p);
    float4 r1 = *(const float4*)(p + WW);
    float4 r2 = *(const float4*)(p + 2 * WW);
    float4 r3 = *(const float4*)(p + 3 * WW);
    float4 r4;
    if (rg < 31) {
        r4 = *(const float4*)(p + 4 * WW);
    } else {
        r4 = make_float4(0.0f, 0.0f, 0.0f, 0.0f);  // row 128 -> zero
    }

    // Next lane's .x = this thread's column x+4 neighbor. Lane 31 = image edge.
    float n0 = __shfl_down_sync(0xffffffffu, r0.x, 1);
    float n1 = __shfl_down_sync(0xffffffffu, r1.x, 1);
    float n2 = __shfl_down_sync(0xffffffffu, r2.x, 1);
    float n3 = __shfl_down_sync(0xffffffffu, r3.x, 1);
    float n4 = __shfl_down_sync(0xffffffffu, r4.x, 1);
    if (lane == 31) { n0 = n1 = n2 = n3 = n4 = 0.0f; }

    float* q = out + base;

    float4 o;
    // row 0
    o.x = w11 * r0.x + w13 * r0.y + w31 * r1.x + w33 * r1.y;
    o.y = w11 * r0.y + w13 * r0.z + w31 * r1.y + w33 * r1.z;
    o.z = w11 * r0.z + w13 * r0.w + w31 * r1.z + w33 * r1.w;
    o.w = w11 * r0.w + w13 * n0   + w31 * r1.w + w33 * n1;
    *(float4*)(q) = o;

    // row 1
    o.x = w11 * r1.x + w13 * r1.y + w31 * r2.x + w33 * r2.y;
    o.y = w11 * r1.y + w13 * r1.z + w31 * r2.y + w33 * r2.z;
    o.z = w11 * r1.z + w13 * r1.w + w31 * r2.z + w33 * r2.w;
    o.w = w11 * r1.w + w13 * n1   + w31 * r2.w + w33 * n2;
    *(float4*)(q + WW) = o;

    // row 2
    o.x = w11 * r2.x + w13 * r2.y + w31 * r3.x + w33 * r3.y;
    o.y = w11 * r2.y + w13 * r2.z + w31 * r3.y + w33 * r3.z;
    o.z = w11 * r2.z + w13 * r2.w + w31 * r3.z + w33 * r3.w;
    o.w = w11 * r2.w + w13 * n2   + w31 * r3.w + w33 * n3;
    *(float4*)(q + 2 * WW) = o;

    // row 3
    o.x = w11 * r3.x + w13 * r3.y + w31 * r4.x + w33 * r4.y;
    o.y = w11 * r3.y + w13 * r3.z + w31 * r4.y + w33 * r4.z;
    o.z = w11 * r3.z + w13 * r3.w + w31 * r4.z + w33 * r4.w;
    o.w = w11 * r3.w + w13 * n3   + w31 * r4.w + w33 * n4;
    *(float4*)(q + 3 * WW) = o;
}

extern "C" void kernel_launch(void* const* d_in, const int* in_sizes, int n_in,
                              void* d_out, int out_size)
{
    const float* x    = (const float*)d_in[0];
    const float* filt = (const float*)d_in[1];
    float* out        = (float*)d_out;

    // warps = B*C*(H/R) = 2048*32 = 65536; 8 warps/block -> 8192 blocks
    const int block = 256;
    const int grid  = (BB * CC * (HH / RR) * 32) / block;
    blur_kernel<<<grid, block>>>(x, filt, out);
}